// round 13
// baseline (speedup 1.0000x reference)
#include <cuda_runtime.h>
#include <cstdint>

// ---------------------------------------------------------------------------
// LocalGate: N=131072, D=1024, E=64, K=2, GATE_ST.
// HYBRID gate: block-striped dual engine, both pipes of every SM busy:
//  - tensor blocks ((bid&63)<29): fp16 m16n8k16 mma.sync (HMMA pipe), fast
//    top-3 + near-tie flagging (TAU) -> exact repair pass afterwards.
//  - fma blocks: FFMA2 diagonal-paired GEMM, Eigen two-panel fp32 numerics,
//    bitwise == XLA:CPU reference (exact, no repair needed).
// Then: repair (flagged) -> hist -> scan -> rank counting sort.
// ---------------------------------------------------------------------------

#define NTOK   131072
#define MDIM   1024
#define NEXP   64
#define NK     (NTOK * 2)
#define TM     128
#define THREADS 128
#define NBLK   (NTOK / TM)          // 1024

// ---- fma-path geometry (R12, proven) ----
#define KC     16
#define NCH    (MDIM / KC)          // 64
#define HALF_CH 32                  // Eigen kc=512 panel boundary
#define AST    132
#define BST    96
#define AWORDS (KC * AST)           // 2112
#define BWORDS (KC * BST)           // 1536
#define STGW   (AWORDS + BWORDS)    // 3648 words
#define STGB   (STGW * 4)           // 14592 B
#define NSTG   3

// ---- tensor-path geometry (R11, proven) ----
#define T_ASTR  24
#define T_BSTR  12
#define T_ABYT  (TM * T_ASTR * 4)       // 12288
#define T_BBYT  (NEXP * T_BSTR * 4)     // 3072
#define T_STGB  (T_ABYT + T_BBYT)       // 15360
#define T_STGF  (T_STGB / 4)            // 3840
#define T_NSTG  4

#define GK_SMEM (T_NSTG * T_STGB)       // 61440 (max of both paths) -> 3 CTAs/SM

#define TAU   3.0e-3f

#define SORT_BLOCKS 512
#define SORT_CHUNK  (NK / SORT_BLOCKS)  // 512

#define FIX_PER_BLK 32
#define REPAIR_BLOCKS 128
#define RP_XS   0
#define RP_WS   (32 * 1024)
#define RP_LG   (RP_WS + 16 * 1024)
#define RP_SMEM ((RP_LG + 32 * 64) * 4)

__device__ unsigned char g_flat[NK];
__device__ int      g_bh[SORT_BLOCKS * NEXP];
__device__ int      g_start[NEXP];
__device__ int      g_fix[NTOK];
__device__ int      g_nfix;
__device__ float    g_wpad[NCH * KC * BST];      // fma path W layout
__device__ uint32_t g_whalf[NEXP * MDIM / 2];    // tensor path W as f16x2
__device__ float    g_panelL[NTOK * NEXP];       // fma panel-L spill

__device__ __forceinline__ uint32_t smem_u32(const void* p) {
    uint32_t a;
    asm("{ .reg .u64 t; cvta.to.shared.u64 t, %1; cvt.u32.u64 %0, t; }" : "=r"(a) : "l"(p));
    return a;
}
__device__ __forceinline__ void cp16(uint32_t dst, const void* src) {
    asm volatile("cp.async.cg.shared.global [%0], [%1], 16;" :: "r"(dst), "l"(src) : "memory");
}
__device__ __forceinline__ void ffma2(float2& d, const float2& a, const float2& b) {
    asm("fma.rn.f32x2 %0, %1, %2, %0;"
        : "+l"(*reinterpret_cast<unsigned long long*>(&d))
        : "l"(*reinterpret_cast<const unsigned long long*>(&a)),
          "l"(*reinterpret_cast<const unsigned long long*>(&b)));
}
__device__ __forceinline__ uint32_t f16x2_rn(float x0, float x1) {
    uint32_t r; asm("cvt.rn.f16x2.f32 %0, %1, %2;" : "=r"(r) : "f"(x1), "f"(x0)); return r;
}
__device__ __forceinline__ void mma_f16(float* d, const uint32_t* a, const uint32_t* b) {
    asm volatile(
        "mma.sync.aligned.m16n8k16.row.col.f32.f16.f16.f32 "
        "{%0,%1,%2,%3}, {%4,%5,%6,%7}, {%8,%9}, {%0,%1,%2,%3};"
        : "+f"(d[0]), "+f"(d[1]), "+f"(d[2]), "+f"(d[3])
        : "r"(a[0]), "r"(a[1]), "r"(a[2]), "r"(a[3]), "r"(b[0]), "r"(b[1]));
}

// ---------------------------------------------------------------------------
__global__ void prep_kernel(const float* __restrict__ W)
{
    const int id = blockIdx.x * 256 + threadIdx.x;       // 65536 threads
    if (id < NCH * KC * NEXP) {
        const int c = id >> 10;
        const int k = (id >> 6) & 15;
        const int e = id & 63;
        g_wpad[c * (KC * BST) + k * BST + (e >> 3) * 12 + (e & 7)] =
            W[(size_t)e * MDIM + c * KC + k];
    }
    if (id < NEXP * MDIM / 2) g_whalf[id] = f16x2_rn(W[2 * id], W[2 * id + 1]);
    if (id == 0) g_nfix = 0;
}

// ---------------------------------------------------------------------------
// tensor-path chunk stage (R11)
__device__ __forceinline__ void issue_chunkT(uint32_t sbase, int s,
                                             const float* __restrict__ X,
                                             int tok0, int c, int t)
{
    const uint32_t stg = sbase + (uint32_t)s * T_STGB;
    {
        const int r  = t >> 2;
        const int k4 = t & 3;
        const float* xs = X + (size_t)(tok0 + r) * MDIM + c * KC + k4 * 4;
        const uint32_t adst = stg + r * (T_ASTR * 4) + k4 * 16;
        #pragma unroll
        for (int i = 0; i < 4; ++i)
            cp16(adst + i * 32 * (T_ASTR * 4), xs + (size_t)i * 32 * MDIM);
    }
    {
        const int r = t >> 1;
        const int h = t & 1;
        const uint32_t* ws = g_whalf + (size_t)r * (MDIM / 2) + c * 8 + h * 4;
        cp16(stg + T_ABYT + r * (T_BSTR * 4) + h * 16, ws);
    }
    asm volatile("cp.async.commit_group;" ::: "memory");
}

__device__ void gate_tensor(const float* __restrict__ X,
                            float* __restrict__ probs_out,
                            float* __restrict__ cw_out,
                            float* smf, float* inv, int tok0)
{
    const uint32_t sbase = smem_u32(smf);
    const int t    = threadIdx.x;
    const int wid  = t >> 5;
    const int lane = t & 31;

    float acc[2][8][4];
    #pragma unroll
    for (int mt = 0; mt < 2; ++mt)
        #pragma unroll
        for (int nt = 0; nt < 8; ++nt)
            #pragma unroll
            for (int i = 0; i < 4; ++i) acc[mt][nt][i] = 0.f;

    issue_chunkT(sbase, 0, X, tok0, 0, t);
    issue_chunkT(sbase, 1, X, tok0, 1, t);
    issue_chunkT(sbase, 2, X, tok0, 2, t);

    const int gr = lane >> 2;
    const int ac = lane & 3;

    for (int c = 0; c < NCH; ++c) {
        if (c < NCH - 2)       asm volatile("cp.async.wait_group 2;" ::: "memory");
        else if (c == NCH - 2) asm volatile("cp.async.wait_group 1;" ::: "memory");
        else                   asm volatile("cp.async.wait_group 0;" ::: "memory");
        __syncthreads();
        if (c + 3 < NCH) issue_chunkT(sbase, (c + 3) & 3, X, tok0, c + 3, t);

        const float*    Ab = smf + (size_t)(c & 3) * T_STGF;
        const uint32_t* Bw = reinterpret_cast<const uint32_t*>(Ab + TM * T_ASTR);

        uint32_t a[2][4], b[8][2];
        #pragma unroll
        for (int mt = 0; mt < 2; ++mt) {
            const int r0 = wid * 32 + mt * 16 + gr;
            const float2 x0 = *(const float2*)(Ab + r0 * T_ASTR + 2 * ac);
            const float2 x1 = *(const float2*)(Ab + (r0 + 8) * T_ASTR + 2 * ac);
            const float2 x2 = *(const float2*)(Ab + r0 * T_ASTR + 2 * ac + 8);
            const float2 x3 = *(const float2*)(Ab + (r0 + 8) * T_ASTR + 2 * ac + 8);
            a[mt][0] = f16x2_rn(x0.x, x0.y);
            a[mt][1] = f16x2_rn(x1.x, x1.y);
            a[mt][2] = f16x2_rn(x2.x, x2.y);
            a[mt][3] = f16x2_rn(x3.x, x3.y);
        }
        #pragma unroll
        for (int nt = 0; nt < 8; ++nt) {
            const uint32_t* bp = Bw + (nt * 8 + gr) * T_BSTR + ac;
            b[nt][0] = bp[0];
            b[nt][1] = bp[4];
        }
        #pragma unroll
        for (int mt = 0; mt < 2; ++mt)
            #pragma unroll
            for (int nt = 0; nt < 8; ++nt)
                mma_f16(acc[mt][nt], a[mt], b[nt]);
    }
    __syncthreads();

    float* L = smf;                  // [128][65]
    #pragma unroll
    for (int mt = 0; mt < 2; ++mt) {
        const int r0 = wid * 32 + mt * 16 + gr;
        #pragma unroll
        for (int nt = 0; nt < 8; ++nt) {
            const int n0 = nt * 8 + ac * 2;
            L[r0 * 65 + n0]           = acc[mt][nt][0];
            L[r0 * 65 + n0 + 1]       = acc[mt][nt][1];
            L[(r0 + 8) * 65 + n0]     = acc[mt][nt][2];
            L[(r0 + 8) * 65 + n0 + 1] = acc[mt][nt][3];
        }
    }
    __syncthreads();

    {
        float* row = L + t * 65;
        float v1 = -1e30f, v2 = -1e30f, v3 = -1e30f; int i1 = 0, i2 = 0;
        #pragma unroll
        for (int e = 0; e < NEXP; ++e) {
            const float v = row[e];
            if (v > v1)      { v3 = v2; v2 = v1; i2 = i1; v1 = v; i1 = e; }
            else if (v > v2) { v3 = v2; v2 = v;  i2 = e; }
            else if (v > v3) { v3 = v; }
        }
        const int tok = tok0 + t;
        g_flat[(size_t)tok * 2]     = (unsigned char)i1;
        g_flat[(size_t)tok * 2 + 1] = (unsigned char)i2;
        if ((v1 - v2 < TAU) || (v2 - v3 < TAU)) {
            const int j = atomicAdd(&g_nfix, 1);
            if (j < NTOK) g_fix[j] = tok;
        }
        float s = 0.f;
        #pragma unroll
        for (int e = 0; e < NEXP; ++e) {
            const float ex = __expf(row[e] - v1);
            s += ex;
            row[e] = ex;
        }
        inv[t] = 1.0f / s;
    }
    __syncthreads();

    float* pbase = probs_out + (size_t)tok0 * NEXP;
    #pragma unroll
    for (int q = 0; q < (TM * NEXP) / 128; ++q) {
        const int idx = t + q * 128;
        pbase[idx] = L[(idx >> 6) * 65 + (idx & 63)] * inv[idx >> 6];
    }
    cw_out[2 * tok0 + t]       = 1.0f;
    cw_out[2 * tok0 + 128 + t] = 1.0f;
}

// ---------------------------------------------------------------------------
__device__ void gate_fma(const float* __restrict__ X,
                         float* __restrict__ probs_out,
                         float* __restrict__ cw_out,
                         float* smf, int bid, int tok0)
{
    const uint32_t sbase = smem_u32(smf);
    const int t    = threadIdx.x;
    const int w    = t >> 5;
    const int lane = t & 31;
    const int tg   = lane >> 3;
    const int eg   = lane & 7;

    const int lr  = t >> 2;
    const int lk4 = t & 3;
    const float* xrow = X + (size_t)(tok0 + lr) * MDIM + lk4 * 4;

    float2 acc1[4][4], acc2[4][4];
    #pragma unroll
    for (int q = 0; q < 4; ++q)
        #pragma unroll
        for (int j = 0; j < 4; ++j) {
            acc1[q][j] = make_float2(0.f, 0.f);
            acc2[q][j] = make_float2(0.f, 0.f);
        }
    float4 pf[4];

    auto cpB = [&](int c) {
        const int s = c % NSTG;
        const float* src = g_wpad + (size_t)c * (KC * BST);
        const uint32_t dst = sbase + s * STGB + AWORDS * 4;
        #pragma unroll
        for (int q = 0; q < 3; ++q)
            cp16(dst + (t + q * THREADS) * 16, src + (t + q * THREADS) * 4);
        asm volatile("cp.async.commit_group;" ::: "memory");
    };
    auto stsA = [&](int c) {
        float* As = smf + (c % NSTG) * STGW;
        #pragma unroll
        for (int i = 0; i < 4; ++i) {
            const int row = lr + 32 * i;
            As[(lk4 * 4 + 0) * AST + row] = pf[i].x;
            As[(lk4 * 4 + 1) * AST + row] = pf[i].y;
            As[(lk4 * 4 + 2) * AST + row] = pf[i].z;
            As[(lk4 * 4 + 3) * AST + row] = pf[i].w;
        }
    };

    #pragma unroll
    for (int i = 0; i < 4; ++i) pf[i] = *(const float4*)(xrow + (size_t)i * 32 * MDIM);
    cpB(0); cpB(1);
    stsA(0);
    #pragma unroll
    for (int i = 0; i < 4; ++i) pf[i] = *(const float4*)(xrow + (size_t)i * 32 * MDIM + KC);
    asm volatile("cp.async.wait_group 1;" ::: "memory");
    __syncthreads();

    for (int c = 0; c < NCH; ++c) {
        const int s = c % NSTG;
        if (c + 2 < NCH) cpB(c + 2);

        const float* As = smf + s * STGW;
        const float* Bs = As + AWORDS;
        #pragma unroll
        for (int k = 0; k < KC; ++k) {
            const float* ak = As + k * AST + w * 32 + tg * 8;
            const float* bk = Bs + k * BST + eg * 12;
            float2 a[4], b[4], bs[4];
            #pragma unroll
            for (int q = 0; q < 4; ++q) a[q] = *(const float2*)(ak + 2 * q);
            #pragma unroll
            for (int j = 0; j < 4; ++j) b[j] = *(const float2*)(bk + 2 * j);
            #pragma unroll
            for (int j = 0; j < 4; ++j) bs[j] = make_float2(b[j].y, b[j].x);
            #pragma unroll
            for (int q = 0; q < 4; ++q)
                #pragma unroll
                for (int j = 0; j < 4; ++j) {
                    ffma2(acc1[q][j], a[q], b[j]);
                    ffma2(acc2[q][j], a[q], bs[j]);
                }
        }
        if (c + 1 < NCH) stsA(c + 1);
        if (c + 2 < NCH) {
            const float* xs = xrow + (c + 2) * KC;
            #pragma unroll
            for (int i = 0; i < 4; ++i) pf[i] = *(const float4*)(xs + (size_t)i * 32 * MDIM);
        }
        if (c + 2 < NCH) { asm volatile("cp.async.wait_group 1;" ::: "memory"); }
        else             { asm volatile("cp.async.wait_group 0;" ::: "memory"); }
        __syncthreads();

        if (c == HALF_CH - 1) {
            float* pl = g_panelL + ((size_t)(bid * 4 + w)) * 2048 + lane * 4;
            #pragma unroll
            for (int q = 0; q < 4; ++q)
                #pragma unroll
                for (int jp = 0; jp < 2; ++jp) {
                    *(float4*)(pl + (q * 2 + jp) * 128) =
                        make_float4(acc1[q][2*jp].x, acc1[q][2*jp].y,
                                    acc1[q][2*jp+1].x, acc1[q][2*jp+1].y);
                    *(float4*)(pl + (8 + q * 2 + jp) * 128) =
                        make_float4(acc2[q][2*jp].x, acc2[q][2*jp].y,
                                    acc2[q][2*jp+1].x, acc2[q][2*jp+1].y);
                }
            #pragma unroll
            for (int q = 0; q < 4; ++q)
                #pragma unroll
                for (int j = 0; j < 4; ++j) {
                    acc1[q][j] = make_float2(0.f, 0.f);
                    acc2[q][j] = make_float2(0.f, 0.f);
                }
        }
    }

    {
        const float* pl = g_panelL + ((size_t)(bid * 4 + w)) * 2048 + lane * 4;
        #pragma unroll
        for (int q = 0; q < 4; ++q)
            #pragma unroll
            for (int jp = 0; jp < 2; ++jp) {
                float4 v1 = *(const float4*)(pl + (q * 2 + jp) * 128);
                float4 v2 = *(const float4*)(pl + (8 + q * 2 + jp) * 128);
                acc1[q][2*jp].x   += v1.x; acc1[q][2*jp].y   += v1.y;
                acc1[q][2*jp+1].x += v1.z; acc1[q][2*jp+1].y += v1.w;
                acc2[q][2*jp].x   += v2.x; acc2[q][2*jp].y   += v2.y;
                acc2[q][2*jp+1].x += v2.z; acc2[q][2*jp+1].y += v2.w;
            }
    }

    #pragma unroll
    for (int p = 0; p < 8; ++p) {
        const int q = p >> 1, r = p & 1;
        float lg[8];
        #pragma unroll
        for (int j = 0; j < 4; ++j) {
            lg[2*j]   = r ? acc2[q][j].y : acc1[q][j].x;
            lg[2*j+1] = r ? acc1[q][j].y : acc2[q][j].x;
        }
        float v1 = -1e30f, v2 = -1e30f; int i1 = 0, i2 = 0;
        #pragma unroll
        for (int m = 0; m < 8; ++m) {
            const float v = lg[m]; const int e = eg * 8 + m;
            if (v > v1)      { v2 = v1; i2 = i1; v1 = v; i1 = e; }
            else if (v > v2) { v2 = v;  i2 = e; }
        }
        #pragma unroll
        for (int msk = 1; msk < 8; msk <<= 1) {
            const float ov1 = __shfl_xor_sync(0xffffffffu, v1, msk);
            const int   oi1 = __shfl_xor_sync(0xffffffffu, i1, msk);
            const float ov2 = __shfl_xor_sync(0xffffffffu, v2, msk);
            const int   oi2 = __shfl_xor_sync(0xffffffffu, i2, msk);
            const bool g1 = (ov1 > v1) || (ov1 == v1 && oi1 < i1);
            if (g1) {
                const bool g2 = (v1 > ov2) || (v1 == ov2 && i1 < oi2);
                v2 = g2 ? v1 : ov2; i2 = g2 ? i1 : oi2;
                v1 = ov1; i1 = oi1;
            } else {
                const bool g2 = (ov1 > v2) || (ov1 == v2 && oi1 < i2);
                v2 = g2 ? ov1 : v2; i2 = g2 ? oi1 : i2;
            }
        }
        const int tok = tok0 + w * 32 + tg * 8 + p;
        if (eg == 0) {
            g_flat[(size_t)tok * 2]     = (unsigned char)i1;
            g_flat[(size_t)tok * 2 + 1] = (unsigned char)i2;
        }
        float ex[8], ssum = 0.f;
        #pragma unroll
        for (int m = 0; m < 8; ++m) { ex[m] = __expf(lg[m] - v1); ssum += ex[m]; }
        ssum += __shfl_xor_sync(0xffffffffu, ssum, 1);
        ssum += __shfl_xor_sync(0xffffffffu, ssum, 2);
        ssum += __shfl_xor_sync(0xffffffffu, ssum, 4);
        const float inv = 1.0f / ssum;
        float* pr = probs_out + (size_t)tok * NEXP + eg * 8;
        *(float4*)(pr)     = make_float4(ex[0]*inv, ex[1]*inv, ex[2]*inv, ex[3]*inv);
        *(float4*)(pr + 4) = make_float4(ex[4]*inv, ex[5]*inv, ex[6]*inv, ex[7]*inv);
    }
    cw_out[2 * tok0 + 2 * t]     = 1.0f;
    cw_out[2 * tok0 + 2 * t + 1] = 1.0f;
}

// ---------------------------------------------------------------------------
__global__ void __launch_bounds__(THREADS, 3)
gate_kernel(const float* __restrict__ X,
            float* __restrict__ probs_out, float* __restrict__ cw_out)
{
    extern __shared__ float smf[];
    __shared__ float inv[TM];
    const int bid  = blockIdx.x;
    const int tok0 = bid * TM;
    if ((bid & 63) < 29)                      // ~45.3% of blocks -> tensor pipe
        gate_tensor(X, probs_out, cw_out, smf, inv, tok0);
    else                                      // ~54.7% -> FFMA2 pipe (exact)
        gate_fma(X, probs_out, cw_out, smf, bid, tok0);
}

// ---------------------------------------------------------------------------
// Exact (bitwise-reference) recompute of flagged tokens (tensor blocks only)
__global__ void __launch_bounds__(256)
repair_kernel(const float* __restrict__ X, const float* __restrict__ W)
{
    extern __shared__ float rsm[];
    float* XS = rsm + RP_XS;
    float* WS = rsm + RP_WS;
    float* LG = rsm + RP_LG;
    const int t  = threadIdx.x;
    const int ts = t >> 3;
    const int el = t & 7;

    const int nf = g_nfix;
    for (int base = blockIdx.x * FIX_PER_BLK; base < nf; base += gridDim.x * FIX_PER_BLK) {
        const int nt = min(FIX_PER_BLK, nf - base);
        __syncthreads();
        for (int i = 0; i < 32; ++i) {
            const int idx = t + i * 256;
            const int row = idx >> 8, c4 = idx & 255;
            if (row < nt) {
                const int tok = g_fix[base + row];
                *(float4*)(XS + row * 1024 + c4 * 4) =
                    *(const float4*)(X + (size_t)tok * MDIM + c4 * 4);
            }
        }
        for (int eg = 0; eg < 4; ++eg) {
            __syncthreads();
            #pragma unroll
            for (int i = 0; i < 16; ++i) {
                const int idx = t + i * 256;
                const int row = idx >> 8, c4 = idx & 255;
                *(float4*)(WS + row * 1024 + c4 * 4) =
                    *(const float4*)(W + (size_t)(eg * 16 + row) * MDIM + c4 * 4);
            }
            __syncthreads();
            if (ts < nt) {
                const float* xr  = XS + ts * 1024;
                const float* wr0 = WS + el * 1024;
                const float* wr1 = WS + (el + 8) * 1024;
                float a0 = 0.f, a1 = 0.f, b0 = 0.f, b1 = 0.f;
                for (int k = 0; k < 512; k += 4) {
                    const float4 x0 = *(const float4*)(xr + k);
                    const float4 x1 = *(const float4*)(xr + 512 + k);
                    const float4 wa0 = *(const float4*)(wr0 + k);
                    const float4 wa1 = *(const float4*)(wr0 + 512 + k);
                    const float4 wb0 = *(const float4*)(wr1 + k);
                    const float4 wb1 = *(const float4*)(wr1 + 512 + k);
                    a0 = fmaf(x0.x, wa0.x, a0); a1 = fmaf(x1.x, wa1.x, a1);
                    b0 = fmaf(x0.x, wb0.x, b0); b1 = fmaf(x1.x, wb1.x, b1);
                    a0 = fmaf(x0.y, wa0.y, a0); a1 = fmaf(x1.y, wa1.y, a1);
                    b0 = fmaf(x0.y, wb0.y, b0); b1 = fmaf(x1.y, wb1.y, b1);
                    a0 = fmaf(x0.z, wa0.z, a0); a1 = fmaf(x1.z, wa1.z, a1);
                    b0 = fmaf(x0.z, wb0.z, b0); b1 = fmaf(x1.z, wb1.z, b1);
                    a0 = fmaf(x0.w, wa0.w, a0); a1 = fmaf(x1.w, wa1.w, a1);
                    b0 = fmaf(x0.w, wb0.w, b0); b1 = fmaf(x1.w, wb1.w, b1);
                }
                LG[ts * 64 + eg * 16 + el]     = a0 + a1;
                LG[ts * 64 + eg * 16 + el + 8] = b0 + b1;
            }
        }
        __syncthreads();
        if (t < nt) {
            const float* row = LG + t * 64;
            float v1 = -1e30f, v2 = -1e30f; int i1 = 0, i2 = 0;
            #pragma unroll
            for (int e = 0; e < NEXP; ++e) {
                const float v = row[e];
                if (v > v1)      { v2 = v1; i2 = i1; v1 = v; i1 = e; }
                else if (v > v2) { v2 = v;  i2 = e; }
            }
            const int tok = g_fix[base + t];
            g_flat[(size_t)tok * 2]     = (unsigned char)i1;
            g_flat[(size_t)tok * 2 + 1] = (unsigned char)i2;
        }
    }
}

// ---------------------------------------------------------------------------
// Counting sort: hist -> scan -> rank
// ---------------------------------------------------------------------------
__global__ void hist_kernel()
{
    __shared__ int h[NEXP];
    const int t = threadIdx.x;
    if (t < NEXP) h[t] = 0;
    __syncthreads();
    const int base = blockIdx.x * SORT_CHUNK;
    #pragma unroll
    for (int q = 0; q < SORT_CHUNK / 256; ++q)
        atomicAdd(&h[g_flat[base + t + q * 256]], 1);
    __syncthreads();
    if (t < NEXP) g_bh[blockIdx.x * NEXP + t] = h[t];
}

__global__ void scan_kernel(float* __restrict__ splits_out)
{
    __shared__ int tot[NEXP];
    const int w    = threadIdx.x >> 5;
    const int lane = threadIdx.x & 31;
    #pragma unroll
    for (int ee = 0; ee < 2; ++ee) {
        const int e = w * 2 + ee;
        int v[16], s = 0;
        #pragma unroll
        for (int i = 0; i < 16; ++i) v[i] = g_bh[(lane * 16 + i) * NEXP + e];
        #pragma unroll
        for (int i = 0; i < 16; ++i) { const int x = v[i]; v[i] = s; s += x; }
        int run = s;
        #pragma unroll
        for (int off = 1; off < 32; off <<= 1) {
            const int n = __shfl_up_sync(0xffffffffu, run, off);
            if (lane >= off) run += n;
        }
        const int excl = run - s;
        #pragma unroll
        for (int i = 0; i < 16; ++i) g_bh[(lane * 16 + i) * NEXP + e] = v[i] + excl;
        if (lane == 31) tot[e] = run;
    }
    __syncthreads();
    if (threadIdx.x < NEXP) splits_out[threadIdx.x] = (float)tot[threadIdx.x];
    if (threadIdx.x == 0) {
        int base = 0;
        for (int e = 0; e < NEXP; ++e) { g_start[e] = base; base += tot[e]; }
    }
}

__global__ void rank_kernel(float* __restrict__ to_out, float* __restrict__ ro_out)
{
    __shared__ int cnt[NEXP];
    const int lane = threadIdx.x;
    cnt[lane]      = g_start[lane]      + g_bh[blockIdx.x * NEXP + lane];
    cnt[lane + 32] = g_start[lane + 32] + g_bh[blockIdx.x * NEXP + lane + 32];
    __syncwarp();
    const int base = blockIdx.x * SORT_CHUNK;
    #pragma unroll
    for (int it = 0; it < SORT_CHUNK / 32; ++it) {
        const int i = base + it * 32 + lane;
        const int e = g_flat[i];
        const unsigned peers = __match_any_sync(0xffffffffu, e);
        const int leader = __ffs(peers) - 1;
        const int prior  = __popc(peers & ((1u << lane) - 1));
        int b = 0;
        if (lane == leader) b = atomicAdd(&cnt[e], __popc(peers));
        b = __shfl_sync(peers, b, leader);
        const int p = b + prior;
        to_out[p] = (float)(i >> 1);
        ro_out[i] = (float)p;
    }
}

// ---------------------------------------------------------------------------
extern "C" void kernel_launch(void* const* d_in, const int* in_sizes, int n_in,
                              void* d_out, int out_size)
{
    const float* X = (const float*)d_in[0];   // [131072, 1024]
    const float* W = (const float*)d_in[1];   // [64, 1024]
    float* out = (float*)d_out;

    float* TO  = out;
    float* RO  = out + NK;
    float* CW  = out + 2 * NK;
    float* SPL = out + 3 * NK;
    float* PR  = out + 3 * NK + NEXP;

    cudaFuncSetAttribute(gate_kernel, cudaFuncAttributeMaxDynamicSharedMemorySize, GK_SMEM);
    cudaFuncSetAttribute(repair_kernel, cudaFuncAttributeMaxDynamicSharedMemorySize, RP_SMEM);

    prep_kernel<<<256, 256>>>(W);
    gate_kernel<<<NBLK, THREADS, GK_SMEM>>>(X, PR, CW);
    repair_kernel<<<REPAIR_BLOCKS, 256, RP_SMEM>>>(X, W);
    hist_kernel<<<SORT_BLOCKS, 256>>>();
    scan_kernel<<<1, 1024>>>(SPL);
    rank_kernel<<<SORT_BLOCKS, 32>>>(TO, RO);
}

// round 15
// speedup vs baseline: 1.4946x; 1.4946x over previous
#include <cuda_runtime.h>
#include <cstdint>

// ---------------------------------------------------------------------------
// LocalGate: N=131072, D=1024, E=64, K=2, GATE_ST.
// FFMA2 (fma.rn.f32x2) GEMM with Eigen-two-panel fp32 numerics (bitwise ==
// XLA:CPU reference): logit = fl(chain(k<512) + chain(k>=512)).
// R14: occupancy 3 -> 4 CTAs/SM (wave count 3 -> 2 for the 1024-block grid).
// Outputs: token_ordering | reversed_ordering | cw(=1) | input_splits | probs
// ---------------------------------------------------------------------------

#define NTOK   131072
#define MDIM   1024
#define NEXP   64
#define NK     (NTOK * 2)
#define TM     128
#define THREADS 128
#define KC     16
#define NCH    (MDIM / KC)          // 64
#define HALF_CH 32                  // Eigen kc=512 panel boundary
#define AST    132                  // A row stride (words)
#define BST    96                   // B row stride (words), 8 groups x 12
#define AWORDS (KC * AST)           // 2112
#define BWORDS (KC * BST)           // 1536
#define STGW   (AWORDS + BWORDS)    // 3648 words
#define STGB   (STGW * 4)           // 14592 B
#define NSTG   3
#define GK_SMEM (NSTG * STGB)       // 43776 -> 4 CTAs/SM (175KB/SM)

#define SORT_BLOCKS 512
#define SORT_CHUNK  (NK / SORT_BLOCKS)  // 512

__device__ unsigned char g_flat[NK];
__device__ int   g_bh[SORT_BLOCKS * NEXP];
__device__ int   g_start[NEXP];
__device__ float g_wpad[NCH * KC * BST];   // W re-laid: [c][k][eg*12 + (e&7)]
__device__ float g_panelL[NTOK * NEXP];    // panel-L spill (33.5 MB)

__device__ __forceinline__ uint32_t smem_u32(const void* p) {
    uint32_t a;
    asm("{ .reg .u64 t; cvta.to.shared.u64 t, %1; cvt.u32.u64 %0, t; }" : "=r"(a) : "l"(p));
    return a;
}
__device__ __forceinline__ void cp16(uint32_t dst, const void* src) {
    asm volatile("cp.async.cg.shared.global [%0], [%1], 16;" :: "r"(dst), "l"(src) : "memory");
}
// packed fp32 FMA: per-lane IEEE rn FMA (bitwise == scalar FFMA chain)
__device__ __forceinline__ void ffma2(float2& d, const float2& a, const float2& b) {
    asm("fma.rn.f32x2 %0, %1, %2, %0;"
        : "+l"(*reinterpret_cast<unsigned long long*>(&d))
        : "l"(*reinterpret_cast<const unsigned long long*>(&a)),
          "l"(*reinterpret_cast<const unsigned long long*>(&b)));
}

// ---------------------------------------------------------------------------
__global__ void prep_kernel(const float* __restrict__ W)
{
    const int id = blockIdx.x * 256 + threadIdx.x;       // 65536 threads
    if (id < NCH * KC * NEXP) {
        const int c = id >> 10;          // / (KC*NEXP)
        const int k = (id >> 6) & 15;
        const int e = id & 63;
        g_wpad[c * (KC * BST) + k * BST + (e >> 3) * 12 + (e & 7)] =
            W[(size_t)e * MDIM + c * KC + k];
    }
    if (id < SORT_BLOCKS * NEXP) g_bh[id] = 0;
}

// ---------------------------------------------------------------------------
__global__ void __launch_bounds__(THREADS, 4)
gate_kernel(const float* __restrict__ X,
            float* __restrict__ probs_out, float* __restrict__ cw_out)
{
    extern __shared__ float smf[];
    __shared__ int h[NEXP];
    const uint32_t sbase = smem_u32(smf);
    const int t    = threadIdx.x;
    const int w    = t >> 5;
    const int lane = t & 31;
    const int tg   = lane >> 3;          // token group 0..3
    const int eg   = lane & 7;           // expert group 0..7
    const int tok0 = blockIdx.x * TM;
    if (t < NEXP) h[t] = 0;

    // A staging: thread loads rows lr+32i (i=0..3), float4 at k4=lk4
    const int lr  = t >> 2;              // 0..31
    const int lk4 = t & 3;               // 0..3
    const float* xrow = X + (size_t)(tok0 + lr) * MDIM + lk4 * 4;

    float2 acc1[4][4], acc2[4][4];
    #pragma unroll
    for (int q = 0; q < 4; ++q)
        #pragma unroll
        for (int j = 0; j < 4; ++j) {
            acc1[q][j] = make_float2(0.f, 0.f);
            acc2[q][j] = make_float2(0.f, 0.f);
        }
    float4 pf[4];

    // B chunk copy: whole padded 6144B chunk, 3 cp16/thread
    auto cpB = [&](int c) {
        const int s = c % NSTG;
        const float* src = g_wpad + (size_t)c * (KC * BST);
        const uint32_t dst = sbase + s * STGB + AWORDS * 4;
        #pragma unroll
        for (int q = 0; q < 3; ++q)
            cp16(dst + (t + q * THREADS) * 16, src + (t + q * THREADS) * 4);
        asm volatile("cp.async.commit_group;" ::: "memory");
    };
    // A store (k-major, transposed from pf regs)
    auto stsA = [&](int c) {
        float* As = smf + (c % NSTG) * STGW;
        #pragma unroll
        for (int i = 0; i < 4; ++i) {
            const int row = lr + 32 * i;
            As[(lk4 * 4 + 0) * AST + row] = pf[i].x;
            As[(lk4 * 4 + 1) * AST + row] = pf[i].y;
            As[(lk4 * 4 + 2) * AST + row] = pf[i].z;
            As[(lk4 * 4 + 3) * AST + row] = pf[i].w;
        }
    };

    // prologue: A0 direct, A1 prefetched; B0,B1 in flight
    #pragma unroll
    for (int i = 0; i < 4; ++i) pf[i] = *(const float4*)(xrow + (size_t)i * 32 * MDIM);
    cpB(0); cpB(1);
    stsA(0);
    #pragma unroll
    for (int i = 0; i < 4; ++i) pf[i] = *(const float4*)(xrow + (size_t)i * 32 * MDIM + KC);
    asm volatile("cp.async.wait_group 1;" ::: "memory");
    __syncthreads();

    for (int c = 0; c < NCH; ++c) {
        const int s = c % NSTG;
        if (c + 2 < NCH) cpB(c + 2);

        const float* As = smf + s * STGW;
        const float* Bs = As + AWORDS;
        #pragma unroll
        for (int k = 0; k < KC; ++k) {
            const float* ak = As + k * AST + w * 32 + tg * 8;
            const float* bk = Bs + k * BST + eg * 12;
            float2 a[4], b[4], bs[4];
            #pragma unroll
            for (int q = 0; q < 4; ++q) a[q] = *(const float2*)(ak + 2 * q);
            #pragma unroll
            for (int j = 0; j < 4; ++j) b[j] = *(const float2*)(bk + 2 * j);
            #pragma unroll
            for (int j = 0; j < 4; ++j) bs[j] = make_float2(b[j].y, b[j].x);
            #pragma unroll
            for (int q = 0; q < 4; ++q)
                #pragma unroll
                for (int j = 0; j < 4; ++j) {
                    ffma2(acc1[q][j], a[q], b[j]);
                    ffma2(acc2[q][j], a[q], bs[j]);
                }
        }
        if (c + 1 < NCH) stsA(c + 1);
        if (c + 2 < NCH) {
            const float* xs = xrow + (c + 2) * KC;
            #pragma unroll
            for (int i = 0; i < 4; ++i) pf[i] = *(const float4*)(xs + (size_t)i * 32 * MDIM);
        }
        if (c + 2 < NCH) { asm volatile("cp.async.wait_group 1;" ::: "memory"); }
        else             { asm volatile("cp.async.wait_group 0;" ::: "memory"); }
        __syncthreads();

        if (c == HALF_CH - 1) {          // Eigen panel boundary: spill L, restart
            float* pl = g_panelL + ((size_t)(blockIdx.x * 4 + w)) * 2048 + lane * 4;
            #pragma unroll
            for (int q = 0; q < 4; ++q)
                #pragma unroll
                for (int jp = 0; jp < 2; ++jp) {
                    *(float4*)(pl + (q * 2 + jp) * 128) =
                        make_float4(acc1[q][2*jp].x, acc1[q][2*jp].y,
                                    acc1[q][2*jp+1].x, acc1[q][2*jp+1].y);
                    *(float4*)(pl + (8 + q * 2 + jp) * 128) =
                        make_float4(acc2[q][2*jp].x, acc2[q][2*jp].y,
                                    acc2[q][2*jp+1].x, acc2[q][2*jp+1].y);
                }
            #pragma unroll
            for (int q = 0; q < 4; ++q)
                #pragma unroll
                for (int j = 0; j < 4; ++j) {
                    acc1[q][j] = make_float2(0.f, 0.f);
                    acc2[q][j] = make_float2(0.f, 0.f);
                }
        }
    }

    // final = panelL + panelH (FADD, bitwise == Eigen C += panel updates)
    {
        const float* pl = g_panelL + ((size_t)(blockIdx.x * 4 + w)) * 2048 + lane * 4;
        #pragma unroll
        for (int q = 0; q < 4; ++q)
            #pragma unroll
            for (int jp = 0; jp < 2; ++jp) {
                float4 v1 = *(const float4*)(pl + (q * 2 + jp) * 128);
                float4 v2 = *(const float4*)(pl + (8 + q * 2 + jp) * 128);
                acc1[q][2*jp].x   += v1.x; acc1[q][2*jp].y   += v1.y;
                acc1[q][2*jp+1].x += v1.z; acc1[q][2*jp+1].y += v1.w;
                acc2[q][2*jp].x   += v2.x; acc2[q][2*jp].y   += v2.y;
                acc2[q][2*jp+1].x += v2.z; acc2[q][2*jp+1].y += v2.w;
            }
    }

    // ---- epilogue: per-token top-2 (exact) + softmax probs ----
    #pragma unroll
    for (int p = 0; p < 8; ++p) {
        const int q = p >> 1, r = p & 1;
        float lg[8];
        #pragma unroll
        for (int j = 0; j < 4; ++j) {
            lg[2*j]   = r ? acc2[q][j].y : acc1[q][j].x;
            lg[2*j+1] = r ? acc1[q][j].y : acc2[q][j].x;
        }
        float v1 = -1e30f, v2 = -1e30f; int i1 = 0, i2 = 0;
        #pragma unroll
        for (int m = 0; m < 8; ++m) {
            const float v = lg[m]; const int e = eg * 8 + m;
            if (v > v1)      { v2 = v1; i2 = i1; v1 = v; i1 = e; }
            else if (v > v2) { v2 = v;  i2 = e; }
        }
        #pragma unroll
        for (int msk = 1; msk < 8; msk <<= 1) {
            const float ov1 = __shfl_xor_sync(0xffffffffu, v1, msk);
            const int   oi1 = __shfl_xor_sync(0xffffffffu, i1, msk);
            const float ov2 = __shfl_xor_sync(0xffffffffu, v2, msk);
            const int   oi2 = __shfl_xor_sync(0xffffffffu, i2, msk);
            const bool g1 = (ov1 > v1) || (ov1 == v1 && oi1 < i1);
            if (g1) {
                const bool g2 = (v1 > ov2) || (v1 == ov2 && i1 < oi2);
                v2 = g2 ? v1 : ov2; i2 = g2 ? i1 : oi2;
                v1 = ov1; i1 = oi1;
            } else {
                const bool g2 = (ov1 > v2) || (ov1 == v2 && oi1 < i2);
                v2 = g2 ? ov1 : v2; i2 = g2 ? oi1 : i2;
            }
        }
        const int tok = tok0 + w * 32 + tg * 8 + p;
        if (eg == 0) {
            g_flat[(size_t)tok * 2]     = (unsigned char)i1;
            g_flat[(size_t)tok * 2 + 1] = (unsigned char)i2;
            atomicAdd(&h[i1], 1);
            atomicAdd(&h[i2], 1);
        }
        float ex[8], ssum = 0.f;
        #pragma unroll
        for (int m = 0; m < 8; ++m) { ex[m] = __expf(lg[m] - v1); ssum += ex[m]; }
        ssum += __shfl_xor_sync(0xffffffffu, ssum, 1);
        ssum += __shfl_xor_sync(0xffffffffu, ssum, 2);
        ssum += __shfl_xor_sync(0xffffffffu, ssum, 4);
        const float inv = 1.0f / ssum;
        float* pr = probs_out + (size_t)tok * NEXP + eg * 8;
        *(float4*)(pr)     = make_float4(ex[0]*inv, ex[1]*inv, ex[2]*inv, ex[3]*inv);
        *(float4*)(pr + 4) = make_float4(ex[4]*inv, ex[5]*inv, ex[6]*inv, ex[7]*inv);
    }
    cw_out[2 * tok0 + 2 * t]     = 1.0f;     // straight-through forward value
    cw_out[2 * tok0 + 2 * t + 1] = 1.0f;
    __syncthreads();
    if (t < NEXP) atomicAdd(&g_bh[(blockIdx.x >> 1) * NEXP + t], h[t]);
}

// ---------------------------------------------------------------------------
// Counting sort: scan -> rank (hist fused into gate)
// ---------------------------------------------------------------------------
__global__ void scan_kernel(float* __restrict__ splits_out)
{
    __shared__ int tot[NEXP];
    const int w    = threadIdx.x >> 5;
    const int lane = threadIdx.x & 31;
    #pragma unroll
    for (int ee = 0; ee < 2; ++ee) {
        const int e = w * 2 + ee;
        int v[16], s = 0;
        #pragma unroll
        for (int i = 0; i < 16; ++i) v[i] = g_bh[(lane * 16 + i) * NEXP + e];
        #pragma unroll
        for (int i = 0; i < 16; ++i) { const int x = v[i]; v[i] = s; s += x; }
        int run = s;
        #pragma unroll
        for (int off = 1; off < 32; off <<= 1) {
            const int n = __shfl_up_sync(0xffffffffu, run, off);
            if (lane >= off) run += n;
        }
        const int excl = run - s;
        #pragma unroll
        for (int i = 0; i < 16; ++i) g_bh[(lane * 16 + i) * NEXP + e] = v[i] + excl;
        if (lane == 31) tot[e] = run;
    }
    __syncthreads();
    if (threadIdx.x < NEXP) splits_out[threadIdx.x] = (float)tot[threadIdx.x];
    if (threadIdx.x == 0) {
        int base = 0;
        for (int e = 0; e < NEXP; ++e) { g_start[e] = base; base += tot[e]; }
    }
}

__global__ void rank_kernel(float* __restrict__ to_out, float* __restrict__ ro_out)
{
    __shared__ int cnt[NEXP];
    const int lane = threadIdx.x;
    cnt[lane]      = g_start[lane]      + g_bh[blockIdx.x * NEXP + lane];
    cnt[lane + 32] = g_start[lane + 32] + g_bh[blockIdx.x * NEXP + lane + 32];
    __syncwarp();
    const int base = blockIdx.x * SORT_CHUNK;
    #pragma unroll
    for (int it = 0; it < SORT_CHUNK / 32; ++it) {
        const int i = base + it * 32 + lane;
        const int e = g_flat[i];
        const unsigned peers = __match_any_sync(0xffffffffu, e);
        const int leader = __ffs(peers) - 1;
        const int prior  = __popc(peers & ((1u << lane) - 1));
        int b = 0;
        if (lane == leader) b = atomicAdd(&cnt[e], __popc(peers));
        b = __shfl_sync(peers, b, leader);
        const int p = b + prior;
        to_out[p] = (float)(i >> 1);
        ro_out[i] = (float)p;
    }
}

// ---------------------------------------------------------------------------
extern "C" void kernel_launch(void* const* d_in, const int* in_sizes, int n_in,
                              void* d_out, int out_size)
{
    const float* X = (const float*)d_in[0];   // [131072, 1024]
    const float* W = (const float*)d_in[1];   // [64, 1024]
    float* out = (float*)d_out;

    float* TO  = out;
    float* RO  = out + NK;
    float* CW  = out + 2 * NK;
    float* SPL = out + 3 * NK;
    float* PR  = out + 3 * NK + NEXP;

    cudaFuncSetAttribute(gate_kernel, cudaFuncAttributeMaxDynamicSharedMemorySize, GK_SMEM);

    prep_kernel<<<256, 256>>>(W);
    gate_kernel<<<NTOK / TM, THREADS, GK_SMEM>>>(X, PR, CW);
    scan_kernel<<<1, 1024>>>(SPL);
    rank_kernel<<<SORT_BLOCKS, 32>>>(TO, RO);
}